// round 11
// baseline (speedup 1.0000x reference)
#include <cuda_runtime.h>
#include <cuda_fp16.h>
#include <cstddef>
#include <cstdint>

// Problem constants (fixed by the dataset)
#define NN   50000
#define EE   800000
#define GG   512
#define CH   128
#define CIN  64
#define NEG_SLOPE 0.01f

#define TILE_M 128
#define GEMM_BLOCKS ((NN + TILE_M - 1) / TILE_M)   // 391
#define CHUNKS (NN / 16)                           // 3125 (NN divisible by 16)
#define NLAYER 12
#define GRID_LAYER 304

// ---------------------------------------------------------------------------
// Device-global scratch
// ---------------------------------------------------------------------------
__device__ __half g_h16A[NN * CH];
__device__ __half g_h16B[NN * CH];
__device__ __half g_agg16[NN * CH];
__device__ __half g_x16[NN * CIN];
__device__ __half g_W16[12 * 128 * 256];   // [layer][n=128][k=256]
__device__ float g_inv[NN];
__device__ int   g_deg[NN];
__device__ int   g_rowptr[NN + 1];
__device__ int   g_cursor[NN];
__device__ int   g_col[EE];
__device__ int   g_gstart[GG + 1];
__device__ int   g_ctrA[NLAYER];                 // agg chunk counters
__device__ int   g_ctrM[NLAYER];                 // gemm tile counters
__device__ int   g_tdone[NLAYER * GEMM_BLOCKS];  // per-tile agg completion

// ---------------------------------------------------------------------------
// Setup: zero deg/counters/flags, cvt x->fp16, build W16, graph bounds.
// ---------------------------------------------------------------------------
__global__ void k_prep(const float* __restrict__ x, const int* __restrict__ batch,
                       const float* __restrict__ Wl0, const float* __restrict__ Wr0,
                       const float* __restrict__ Wl, const float* __restrict__ Wr) {
    int i = blockIdx.x * blockDim.x + threadIdx.x;
    if (i < NN * CIN) g_x16[i] = __float2half_rn(x[i]);
    if (i < 12 * 128 * 256) {
        int l = i >> 15;
        int n = (i >> 8) & 127;
        int k = i & 255;
        float v = 0.0f;
        if (l == 0) {
            if (k < 64)       v = Wl0[k * 128 + n];
            else if (k < 128) v = Wr0[(k - 64) * 128 + n];
        } else {
            int li = l - 1;
            if (k < 128) v = Wl[(size_t)li * 128 * 128 + k * 128 + n];
            else         v = Wr[(size_t)li * 128 * 128 + (k - 128) * 128 + n];
        }
        g_W16[i] = __float2half_rn(v);
    }
    if (i < NN) g_deg[i] = 0;
    if (i < NLAYER) { g_ctrA[i] = 0; g_ctrM[i] = 0; }
    if (i < NLAYER * GEMM_BLOCKS) g_tdone[i] = 0;
    if (i <= GG) {
        int lo = 0, hi = NN;
        while (lo < hi) {
            int mid = (lo + hi) >> 1;
            if (batch[mid] < i) lo = mid + 1; else hi = mid;
        }
        g_gstart[i] = lo;
    }
}

__global__ void k_count(const int* __restrict__ dst) {
    int i = blockIdx.x * blockDim.x + threadIdx.x;
    if (i < EE) atomicAdd(&g_deg[dst[i]], 1);
}

// One-pass scan: 1024 threads, thread t owns 49 contiguous elements.
__global__ void k_scan2() {
    const int NPT = 49;
    const int tid = threadIdx.x;
    const int base = tid * NPT;
    int sum = 0;
    #pragma unroll 1
    for (int j = 0; j < NPT; j++) {
        int i = base + j;
        if (i < NN) sum += g_deg[i];
    }
    const int lane = tid & 31, w = tid >> 5;
    int s = sum;
    #pragma unroll
    for (int o = 1; o < 32; o <<= 1) {
        int t = __shfl_up_sync(0xffffffffu, s, o);
        if (lane >= o) s += t;
    }
    __shared__ int wsum[32];
    if (lane == 31) wsum[w] = s;
    __syncthreads();
    if (w == 0) {
        int ws = wsum[lane];
        #pragma unroll
        for (int o = 1; o < 32; o <<= 1) {
            int t = __shfl_up_sync(0xffffffffu, ws, o);
            if (lane >= o) ws += t;
        }
        wsum[lane] = ws;
    }
    __syncthreads();
    int run = s - sum + (w > 0 ? wsum[w - 1] : 0);
    #pragma unroll 1
    for (int j = 0; j < NPT; j++) {
        int i = base + j;
        if (i < NN) {
            int v = g_deg[i];
            g_rowptr[i] = run;
            g_cursor[i] = run;
            g_inv[i] = 1.0f / (float)max(v, 1);
            run += v;
        }
    }
    if (tid == 1023) g_rowptr[NN] = run;
}

__global__ void k_fill(const int* __restrict__ src, const int* __restrict__ dst) {
    int i = blockIdx.x * blockDim.x + threadIdx.x;
    if (i < EE) {
        int d = dst[i];
        int pos = atomicAdd(&g_cursor[d], 1);
        g_col[pos] = src[i];
    }
}

// ---------------------------------------------------------------------------
// Per-node gather-mean (warp-collective), 4-way unrolled.
// ---------------------------------------------------------------------------
__device__ __forceinline__ void agg_node_128(const __half* __restrict__ Hf,
                                             __half* __restrict__ aggb,
                                             int node, int lane) {
    const int b = g_rowptr[node], e = g_rowptr[node + 1];
    const float iv = g_inv[node];
    const uint2* hp = (const uint2*)Hf;
    float4 a0 = make_float4(0.f, 0.f, 0.f, 0.f);
    float4 a1 = make_float4(0.f, 0.f, 0.f, 0.f);
    float4 a2 = make_float4(0.f, 0.f, 0.f, 0.f);
    float4 a3 = make_float4(0.f, 0.f, 0.f, 0.f);
    int j = b;
    for (; j + 3 < e; j += 4) {
        uint2 u0 = hp[(size_t)g_col[j]     * 32 + lane];
        uint2 u1 = hp[(size_t)g_col[j + 1] * 32 + lane];
        uint2 u2 = hp[(size_t)g_col[j + 2] * 32 + lane];
        uint2 u3 = hp[(size_t)g_col[j + 3] * 32 + lane];
        float2 p;
        p = __half22float2(*(const __half2*)&u0.x); a0.x += p.x; a0.y += p.y;
        p = __half22float2(*(const __half2*)&u0.y); a0.z += p.x; a0.w += p.y;
        p = __half22float2(*(const __half2*)&u1.x); a1.x += p.x; a1.y += p.y;
        p = __half22float2(*(const __half2*)&u1.y); a1.z += p.x; a1.w += p.y;
        p = __half22float2(*(const __half2*)&u2.x); a2.x += p.x; a2.y += p.y;
        p = __half22float2(*(const __half2*)&u2.y); a2.z += p.x; a2.w += p.y;
        p = __half22float2(*(const __half2*)&u3.x); a3.x += p.x; a3.y += p.y;
        p = __half22float2(*(const __half2*)&u3.y); a3.z += p.x; a3.w += p.y;
    }
    for (; j < e; j++) {
        uint2 u0 = hp[(size_t)g_col[j] * 32 + lane];
        float2 p;
        p = __half22float2(*(const __half2*)&u0.x); a0.x += p.x; a0.y += p.y;
        p = __half22float2(*(const __half2*)&u0.y); a0.z += p.x; a0.w += p.y;
    }
    a0.x = (a0.x + a1.x + a2.x + a3.x) * iv;
    a0.y = (a0.y + a1.y + a2.y + a3.y) * iv;
    a0.z = (a0.z + a1.z + a2.z + a3.z) * iv;
    a0.w = (a0.w + a1.w + a2.w + a3.w) * iv;
    uint2 o;
    *(__half2*)&o.x = __floats2half2_rn(a0.x, a0.y);
    *(__half2*)&o.y = __floats2half2_rn(a0.z, a0.w);
    ((uint2*)aggb)[(size_t)node * 32 + lane] = o;
}

__device__ __forceinline__ void agg_node_64(const __half* __restrict__ Hf,
                                            __half* __restrict__ aggb,
                                            int node, int lane) {
    const int b = g_rowptr[node], e = g_rowptr[node + 1];
    const float iv = g_inv[node];
    const uint32_t* hp = (const uint32_t*)Hf;
    float2 a0 = make_float2(0.f, 0.f), a1 = make_float2(0.f, 0.f);
    float2 a2 = make_float2(0.f, 0.f), a3 = make_float2(0.f, 0.f);
    int j = b;
    for (; j + 3 < e; j += 4) {
        uint32_t u0 = hp[(size_t)g_col[j]     * 32 + lane];
        uint32_t u1 = hp[(size_t)g_col[j + 1] * 32 + lane];
        uint32_t u2 = hp[(size_t)g_col[j + 2] * 32 + lane];
        uint32_t u3 = hp[(size_t)g_col[j + 3] * 32 + lane];
        float2 p;
        p = __half22float2(*(const __half2*)&u0); a0.x += p.x; a0.y += p.y;
        p = __half22float2(*(const __half2*)&u1); a1.x += p.x; a1.y += p.y;
        p = __half22float2(*(const __half2*)&u2); a2.x += p.x; a2.y += p.y;
        p = __half22float2(*(const __half2*)&u3); a3.x += p.x; a3.y += p.y;
    }
    for (; j < e; j++) {
        uint32_t u0 = hp[(size_t)g_col[j] * 32 + lane];
        float2 p = __half22float2(*(const __half2*)&u0);
        a0.x += p.x; a0.y += p.y;
    }
    a0.x = (a0.x + a1.x + a2.x + a3.x) * iv;
    a0.y = (a0.y + a1.y + a2.y + a3.y) * iv;
    uint32_t o;
    *(__half2*)&o = __floats2half2_rn(a0.x, a0.y);
    ((uint32_t*)aggb)[(size_t)node * 32 + lane] = o;
}

// ---------------------------------------------------------------------------
// Merged per-layer kernel: work-stealing agg chunks, then work-stealing GEMM
// tiles gated on per-tile agg completion flags.
// ---------------------------------------------------------------------------
#define AS_STR 40
#define BS_STR 40

__device__ __forceinline__ void cp16(uint32_t dst, const void* src) {
    asm volatile("cp.async.ca.shared.global [%0], [%1], 16;" :: "r"(dst), "l"(src));
}
#define CP_COMMIT() asm volatile("cp.async.commit_group;" ::: "memory")
template <int Nw>
__device__ __forceinline__ void cp_wait() {
    asm volatile("cp.async.wait_group %0;" :: "n"(Nw) : "memory");
}
__device__ __forceinline__ void ldsm4(uint32_t& r0, uint32_t& r1, uint32_t& r2,
                                      uint32_t& r3, uint32_t addr) {
    asm volatile("ldmatrix.sync.aligned.m8n8.x4.shared.b16 {%0,%1,%2,%3}, [%4];"
                 : "=r"(r0), "=r"(r1), "=r"(r2), "=r"(r3) : "r"(addr));
}

template <int KH, int ACT>
__global__ __launch_bounds__(256) void k_layer(
    const __half* __restrict__ Hin,   // [NN][KH] node features (layer input)
    __half* __restrict__ Agg,         // [NN][KH] agg scratch
    const __half* __restrict__ W16,   // [128][256] transposed weights (layer)
    const float* __restrict__ bias,   // [128]
    __half* __restrict__ Out,         // [NN][128]
    int layer)
{
    constexpr int KT = 2 * KH;
    constexpr int NIT = KT / 32;
    __shared__ __half As[2][128 * AS_STR];
    __shared__ __half Bs[2][128 * BS_STR];
    __shared__ int s_tile;

    const int tid = threadIdx.x;
    const int wid = tid >> 5;
    const int lane = tid & 31;
    const int wm = wid & 3;
    const int wn2 = wid >> 2;

    // ================= phase 1: agg chunk stealing (16 nodes/chunk) ========
    for (;;) {
        int chunk;
        if (lane == 0) chunk = atomicAdd(&g_ctrA[layer], 1);
        chunk = __shfl_sync(0xffffffffu, chunk, 0);
        if (chunk >= CHUNKS) break;
        const int n0 = chunk * 16;
        #pragma unroll 1
        for (int i = 0; i < 16; i++) {
            if constexpr (KH == 128) agg_node_128(Hin, Agg, n0 + i, lane);
            else                     agg_node_64(Hin, Agg, n0 + i, lane);
        }
        __threadfence();
        if (lane == 0) atomicAdd(&g_tdone[layer * GEMM_BLOCKS + (chunk >> 3)], 1);
    }

    // ================= phase 2: gemm tile stealing =========================
    const int l7 = lane & 7;
    const int g = lane >> 3;
    const int aRowOff = (g & 1) * 8;
    const int aKOff   = (g & 2) * 4;
    const int bNOff   = (g & 2) * 4;
    const int bKOff   = (g & 1) * 8;
    const int c0 = tid, c1 = tid + 256;

    for (;;) {
        __syncthreads();
        if (tid == 0) s_tile = atomicAdd(&g_ctrM[layer], 1);
        __syncthreads();
        const int t = s_tile;
        if (t >= GEMM_BLOCKS) break;
        // wait for this tile's agg chunks (claimed chunks always complete:
        // their claimant warps are resident)
        if (tid == 0) {
            const int need = min(8, CHUNKS - t * 8);
            volatile int* f = &g_tdone[layer * GEMM_BLOCKS + t];
            while (*f < need) {}
        }
        __syncthreads();
        __threadfence();

        const int m0 = t * TILE_M;

        auto issue = [&](int stg, int kt) {
            #pragma unroll
            for (int cc = 0; cc < 2; cc++) {
                int cch = (cc == 0) ? c0 : c1;
                int r = cch >> 2, part = cch & 3;
                {
                    int m = m0 + r;
                    int mm = (m < NN) ? m : (NN - 1);
                    int kcat = kt + part * 8;
                    const __half* p = (kcat < KH) ? (Agg + (size_t)mm * KH + kcat)
                                                  : (Hin + (size_t)mm * KH + (kcat - KH));
                    uint32_t d = (uint32_t)__cvta_generic_to_shared(&As[stg][r * AS_STR + part * 8]);
                    cp16(d, p);
                }
                {
                    const __half* p = W16 + (size_t)r * 256 + kt + part * 8;
                    uint32_t d = (uint32_t)__cvta_generic_to_shared(&Bs[stg][r * BS_STR + part * 8]);
                    cp16(d, p);
                }
            }
        };

        float c[2][8][4];
        #pragma unroll
        for (int mf = 0; mf < 2; mf++)
            #pragma unroll
            for (int nf = 0; nf < 8; nf++)
                #pragma unroll
                for (int j = 0; j < 4; j++) c[mf][nf][j] = 0.0f;

        issue(0, 0);
        CP_COMMIT();

        #pragma unroll 1
        for (int it = 0; it < NIT; it++) {
            if (it + 1 < NIT) {
                issue((it + 1) & 1, (it + 1) * 32);
                CP_COMMIT();
                cp_wait<1>();
            } else {
                cp_wait<0>();
            }
            __syncthreads();

            const int stg = it & 1;
            const uint32_t aBase = (uint32_t)__cvta_generic_to_shared(&As[stg][0]);
            const uint32_t bBase = (uint32_t)__cvta_generic_to_shared(&Bs[stg][0]);

            #pragma unroll
            for (int s = 0; s < 2; s++) {
                const int kb = s * 16;
                uint32_t a[2][4];
                #pragma unroll
                for (int mf = 0; mf < 2; mf++) {
                    int row = wm * 32 + mf * 16 + l7 + aRowOff;
                    uint32_t addr = aBase + (uint32_t)(row * AS_STR + kb + aKOff) * 2;
                    ldsm4(a[mf][0], a[mf][1], a[mf][2], a[mf][3], addr);
                }
                uint32_t bfr[8][2];
                #pragma unroll
                for (int p = 0; p < 4; p++) {
                    int n = wn2 * 64 + p * 16 + l7 + bNOff;
                    uint32_t addr = bBase + (uint32_t)(n * BS_STR + kb + bKOff) * 2;
                    ldsm4(bfr[2 * p][0], bfr[2 * p][1], bfr[2 * p + 1][0], bfr[2 * p + 1][1], addr);
                }
                #pragma unroll
                for (int mf = 0; mf < 2; mf++) {
                    #pragma unroll
                    for (int nf = 0; nf < 8; nf++) {
                        asm volatile(
                            "mma.sync.aligned.m16n8k16.row.col.f32.f16.f16.f32 "
                            "{%0,%1,%2,%3}, {%4,%5,%6,%7}, {%8,%9}, {%0,%1,%2,%3};"
                            : "+f"(c[mf][nf][0]), "+f"(c[mf][nf][1]),
                              "+f"(c[mf][nf][2]), "+f"(c[mf][nf][3])
                            : "r"(a[mf][0]), "r"(a[mf][1]), "r"(a[mf][2]), "r"(a[mf][3]),
                              "r"(bfr[nf][0]), "r"(bfr[nf][1]));
                    }
                }
            }
            __syncthreads();
        }

        // ---- epilogue ----
        const int colbase = wn2 * 64 + (lane & 3) * 2;
        float2 bb[8];
        #pragma unroll
        for (int nf = 0; nf < 8; nf++)
            bb[nf] = *(const float2*)(bias + colbase + nf * 8);

        #pragma unroll
        for (int mf = 0; mf < 2; mf++) {
            #pragma unroll
            for (int half = 0; half < 2; half++) {
                int m = m0 + wm * 32 + mf * 16 + (lane >> 2) + half * 8;
                if (m < NN) {
                    __half* orow = Out + (size_t)m * CH;
                    #pragma unroll
                    for (int nf = 0; nf < 8; nf++) {
                        float vx = c[mf][nf][half * 2 + 0] + bb[nf].x;
                        float vy = c[mf][nf][half * 2 + 1] + bb[nf].y;
                        if (ACT == 1) {
                            vx = fmaxf(vx, 0.f);
                            vy = fmaxf(vy, 0.f);
                        } else if (ACT == 2) {
                            vx = (vx > 0.f) ? vx : NEG_SLOPE * vx;
                            vy = (vy > 0.f) ? vy : NEG_SLOPE * vy;
                        }
                        *(__half2*)(orow + colbase + nf * 8) = __floats2half2_rn(vx, vy);
                    }
                }
            }
        }
    }
}

// ---------------------------------------------------------------------------
// Fused segment-mean pool + linear head: one block per graph (batch sorted).
// ---------------------------------------------------------------------------
__global__ void k_poolhead(const __half* __restrict__ h,
                           const float* __restrict__ hW, const float* __restrict__ hb,
                           float* __restrict__ out) {
    const int g = blockIdx.x;
    const int t = threadIdx.x;
    const int s = g_gstart[g], e = g_gstart[g + 1];
    float acc = 0.f;
    for (int i = s; i < e; i++)
        acc += __half2float(h[(size_t)i * CH + t]);
    const float iv = 1.0f / (float)max(e - s, 1);
    const float p = acc * iv;
    __shared__ float r0[128], r1[128];
    r0[t] = p * hW[t * 2 + 0];
    r1[t] = p * hW[t * 2 + 1];
    __syncthreads();
    #pragma unroll
    for (int o = 64; o > 0; o >>= 1) {
        if (t < o) { r0[t] += r0[t + o]; r1[t] += r1[t + o]; }
        __syncthreads();
    }
    if (t == 0) {
        out[g * 2 + 0] = r0[0] + hb[0];
        out[g * 2 + 1] = r1[0] + hb[1];
    }
}

// ---------------------------------------------------------------------------
// Host launch
// ---------------------------------------------------------------------------
static void* sym_addr(const void* sym) {
    void* p = nullptr;
    cudaGetSymbolAddress(&p, sym);
    return p;
}

extern "C" void kernel_launch(void* const* d_in, const int* in_sizes, int n_in,
                              void* d_out, int out_size) {
    const float* x    = (const float*)d_in[0];
    const int*   ei   = (const int*)d_in[1];
    const int*   srcp = ei;
    const int*   dstp = ei + EE;
    const int*   batch = (const int*)d_in[2];
    const float* Wl0 = (const float*)d_in[3];
    const float* Wr0 = (const float*)d_in[4];
    const float* b0  = (const float*)d_in[5];
    const float* Wl  = (const float*)d_in[6];
    const float* Wr  = (const float*)d_in[7];
    const float* bb  = (const float*)d_in[8];
    const float* hW  = (const float*)d_in[9];
    const float* hb  = (const float*)d_in[10];
    float* out = (float*)d_out;

    __half* h16A  = (__half*)sym_addr(g_h16A);
    __half* h16B  = (__half*)sym_addr(g_h16B);
    __half* agg16 = (__half*)sym_addr(g_agg16);
    __half* x16   = (__half*)sym_addr(g_x16);
    __half* W16   = (__half*)sym_addr(g_W16);

    const int TPB = 256;

    // --- setup: prep (zero + cvt + W16 + gstart) -> count -> scan -> fill ---
    k_prep<<<(NN * CIN + TPB - 1) / TPB, TPB>>>(x, batch, Wl0, Wr0, Wl, Wr);
    k_count<<<(EE + TPB - 1) / TPB, TPB>>>(dstp);
    k_scan2<<<1, 1024>>>();
    k_fill<<<(EE + TPB - 1) / TPB, TPB>>>(srcp, dstp);

    // --- conv 0 (C_IN=64 -> 128), ReLU ---
    k_layer<64, 1><<<GRID_LAYER, TPB>>>(x16, agg16, W16, b0, h16A, 0);

    // --- convs 1..11 ---
    __half* hcur = h16A;
    __half* hnxt = h16B;
    for (int i = 0; i < 11; i++) {
        int ci = i + 1;
        const __half* wt = W16 + (size_t)(i + 1) * 128 * 256;
        const float* bi = bb + (size_t)i * CH;
        if (ci == 11) {
            k_layer<128, 0><<<GRID_LAYER, TPB>>>(hcur, agg16, wt, bi, hnxt, ci);
        } else if (ci == 3 || ci == 7) {
            k_layer<128, 2><<<GRID_LAYER, TPB>>>(hcur, agg16, wt, bi, hnxt, ci);
        } else {
            k_layer<128, 1><<<GRID_LAYER, TPB>>>(hcur, agg16, wt, bi, hnxt, ci);
        }
        __half* t = hcur; hcur = hnxt; hnxt = t;
    }

    // --- fused global mean pool + head ---
    k_poolhead<<<GG, 128>>>(hcur, hW, hb, out);
}

// round 12
// speedup vs baseline: 1.5473x; 1.5473x over previous
#include <cuda_runtime.h>
#include <cuda_fp16.h>
#include <cstddef>
#include <cstdint>

// Problem constants (fixed by the dataset)
#define NN   50000
#define EE   800000
#define GG   512
#define CH   128
#define CIN  64
#define NEG_SLOPE 0.01f

#define TILE_M 128
#define GEMM_BLOCKS ((NN + TILE_M - 1) / TILE_M)   // 391
#define TILES0 196
#define TILES1 (GEMM_BLOCKS - TILES0)              // 195
#define NSPLIT (TILES0 * TILE_M)                   // 25088

// ---------------------------------------------------------------------------
// Device-global scratch
// ---------------------------------------------------------------------------
__device__ __half g_h16A[NN * CH];
__device__ __half g_h16B[NN * CH];
__device__ __half g_agg16[NN * CH];
__device__ __half g_x16[NN * CIN];
__device__ __half g_W16[12 * 128 * 256];   // [layer][n=128][k=256]
__device__ float g_inv[NN];
__device__ int   g_deg[NN];
__device__ int   g_rowptr[NN + 1];
__device__ int   g_cursor[NN];
__device__ int   g_col[EE];
__device__ int   g_gstart[GG + 1];

// ---------------------------------------------------------------------------
// Utility kernels
// ---------------------------------------------------------------------------
__global__ void k_zero_i(int* p, int n) {
    int i = blockIdx.x * blockDim.x + threadIdx.x;
    if (i < n) p[i] = 0;
}
__global__ void k_count(const int* __restrict__ dst) {
    int i = blockIdx.x * blockDim.x + threadIdx.x;
    if (i < EE) atomicAdd(&g_deg[dst[i]], 1);
}

// One-pass scan: 1024 threads, thread t owns 49 contiguous elements.
__global__ void k_scan2() {
    const int NPT = 49;
    const int tid = threadIdx.x;
    const int base = tid * NPT;
    int sum = 0;
    #pragma unroll 1
    for (int j = 0; j < NPT; j++) {
        int i = base + j;
        if (i < NN) sum += g_deg[i];
    }
    const int lane = tid & 31, w = tid >> 5;
    int s = sum;
    #pragma unroll
    for (int o = 1; o < 32; o <<= 1) {
        int t = __shfl_up_sync(0xffffffffu, s, o);
        if (lane >= o) s += t;
    }
    __shared__ int wsum[32];
    if (lane == 31) wsum[w] = s;
    __syncthreads();
    if (w == 0) {
        int ws = wsum[lane];
        #pragma unroll
        for (int o = 1; o < 32; o <<= 1) {
            int t = __shfl_up_sync(0xffffffffu, ws, o);
            if (lane >= o) ws += t;
        }
        wsum[lane] = ws;
    }
    __syncthreads();
    int run = s - sum + (w > 0 ? wsum[w - 1] : 0);
    #pragma unroll 1
    for (int j = 0; j < NPT; j++) {
        int i = base + j;
        if (i < NN) {
            int v = g_deg[i];
            g_rowptr[i] = run;
            g_cursor[i] = run;
            g_inv[i] = 1.0f / (float)max(v, 1);
            run += v;
        }
    }
    if (tid == 1023) g_rowptr[NN] = run;
}

__global__ void k_fill(const int* __restrict__ src, const int* __restrict__ dst) {
    int i = blockIdx.x * blockDim.x + threadIdx.x;
    if (i < EE) {
        int d = dst[i];
        int pos = atomicAdd(&g_cursor[d], 1);
        g_col[pos] = src[i];
    }
}

// Prep (runs on side stream): cvt x->fp16, build W16, graph bounds.
__global__ void k_prep2(const float* __restrict__ x, const int* __restrict__ batch,
                        const float* __restrict__ Wl0, const float* __restrict__ Wr0,
                        const float* __restrict__ Wl, const float* __restrict__ Wr) {
    int i = blockIdx.x * blockDim.x + threadIdx.x;
    if (i < NN * CIN) g_x16[i] = __float2half_rn(x[i]);
    if (i < 12 * 128 * 256) {
        int l = i >> 15;
        int n = (i >> 8) & 127;
        int k = i & 255;
        float v = 0.0f;
        if (l == 0) {
            if (k < 64)       v = Wl0[k * 128 + n];
            else if (k < 128) v = Wr0[(k - 64) * 128 + n];
        } else {
            int li = l - 1;
            if (k < 128) v = Wl[(size_t)li * 128 * 128 + k * 128 + n];
            else         v = Wr[(size_t)li * 128 * 128 + (k - 128) * 128 + n];
        }
        g_W16[i] = __float2half_rn(v);
    }
    if (i <= GG) {
        int lo = 0, hi = NN;
        while (lo < hi) {
            int mid = (lo + hi) >> 1;
            if (batch[mid] < i) lo = mid + 1; else hi = mid;
        }
        g_gstart[i] = lo;
    }
}

// ---------------------------------------------------------------------------
// Mean aggregation over node slice [nb, ne): one warp per node.
// ---------------------------------------------------------------------------
template <int C>
__global__ void k_agg16(const __half* __restrict__ h, __half* __restrict__ agg,
                        int nb, int ne) {
    int gw = nb + ((blockIdx.x * blockDim.x + threadIdx.x) >> 5);
    if (gw >= ne) return;
    int lane = threadIdx.x & 31;
    int b = g_rowptr[gw], e = g_rowptr[gw + 1];
    float iv = g_inv[gw];
    if constexpr (C == 128) {
        const uint2* hp = (const uint2*)h;
        float4 a0 = make_float4(0.f, 0.f, 0.f, 0.f);
        float4 a1 = make_float4(0.f, 0.f, 0.f, 0.f);
        int j = b;
        for (; j + 1 < e; j += 2) {
            int s0 = g_col[j], s1 = g_col[j + 1];
            uint2 u0 = hp[s0 * 32 + lane];
            uint2 u1 = hp[s1 * 32 + lane];
            float2 p0 = __half22float2(*(const __half2*)&u0.x);
            float2 q0 = __half22float2(*(const __half2*)&u0.y);
            float2 p1 = __half22float2(*(const __half2*)&u1.x);
            float2 q1 = __half22float2(*(const __half2*)&u1.y);
            a0.x += p0.x; a0.y += p0.y; a0.z += q0.x; a0.w += q0.y;
            a1.x += p1.x; a1.y += p1.y; a1.z += q1.x; a1.w += q1.y;
        }
        if (j < e) {
            int s0 = g_col[j];
            uint2 u0 = hp[s0 * 32 + lane];
            float2 p0 = __half22float2(*(const __half2*)&u0.x);
            float2 q0 = __half22float2(*(const __half2*)&u0.y);
            a0.x += p0.x; a0.y += p0.y; a0.z += q0.x; a0.w += q0.y;
        }
        a0.x = (a0.x + a1.x) * iv; a0.y = (a0.y + a1.y) * iv;
        a0.z = (a0.z + a1.z) * iv; a0.w = (a0.w + a1.w) * iv;
        uint2 o;
        *(__half2*)&o.x = __floats2half2_rn(a0.x, a0.y);
        *(__half2*)&o.y = __floats2half2_rn(a0.z, a0.w);
        ((uint2*)agg)[gw * 32 + lane] = o;
    } else {  // C == 64
        const uint32_t* hp = (const uint32_t*)h;
        float2 a0 = make_float2(0.f, 0.f), a1 = make_float2(0.f, 0.f);
        int j = b;
        for (; j + 1 < e; j += 2) {
            int s0 = g_col[j], s1 = g_col[j + 1];
            uint32_t u0 = hp[s0 * 32 + lane];
            uint32_t u1 = hp[s1 * 32 + lane];
            float2 p0 = __half22float2(*(const __half2*)&u0);
            float2 p1 = __half22float2(*(const __half2*)&u1);
            a0.x += p0.x; a0.y += p0.y;
            a1.x += p1.x; a1.y += p1.y;
        }
        if (j < e) {
            uint32_t u0 = hp[g_col[j] * 32 + lane];
            float2 p0 = __half22float2(*(const __half2*)&u0);
            a0.x += p0.x; a0.y += p0.y;
        }
        a0.x = (a0.x + a1.x) * iv; a0.y = (a0.y + a1.y) * iv;
        uint32_t o;
        *(__half2*)&o = __floats2half2_rn(a0.x, a0.y);
        ((uint32_t*)agg)[gw * 32 + lane] = o;
    }
}

// ---------------------------------------------------------------------------
// fp16 mma.sync GEMM, cp.async double-buffered, ldmatrix fragment loads.
// Processes tiles [tile0 .. tile0+gridDim.x).
// ---------------------------------------------------------------------------
#define AS_STR 40
#define BS_STR 40

__device__ __forceinline__ void cp16(uint32_t dst, const void* src) {
    asm volatile("cp.async.ca.shared.global [%0], [%1], 16;" :: "r"(dst), "l"(src));
}
#define CP_COMMIT() asm volatile("cp.async.commit_group;" ::: "memory")
template <int Nw>
__device__ __forceinline__ void cp_wait() {
    asm volatile("cp.async.wait_group %0;" :: "n"(Nw) : "memory");
}
__device__ __forceinline__ void ldsm4(uint32_t& r0, uint32_t& r1, uint32_t& r2,
                                      uint32_t& r3, uint32_t addr) {
    asm volatile("ldmatrix.sync.aligned.m8n8.x4.shared.b16 {%0,%1,%2,%3}, [%4];"
                 : "=r"(r0), "=r"(r1), "=r"(r2), "=r"(r3) : "r"(addr));
}

template <int KH, int ACT>
__global__ __launch_bounds__(256) void k_gemm16(
    const __half* __restrict__ A,    // aggregated fp16, [NN][KH]
    const __half* __restrict__ H,    // node features fp16, [NN][KH]
    const __half* __restrict__ W16,  // [128][256] transposed fp16 weights (layer)
    const float* __restrict__ bias,  // [128]
    __half* __restrict__ Out,        // [NN][128]
    int tile0)
{
    constexpr int KT = 2 * KH;
    constexpr int NIT = KT / 32;
    __shared__ __half As[2][128 * AS_STR];
    __shared__ __half Bs[2][128 * BS_STR];

    const int tid = threadIdx.x;
    const int wid = tid >> 5;
    const int lane = tid & 31;
    const int wm = wid & 3;
    const int wn2 = wid >> 2;
    const int m0 = (tile0 + blockIdx.x) * TILE_M;

    const int c0 = tid, c1 = tid + 256;

    auto issue = [&](int stg, int kt) {
        #pragma unroll
        for (int cc = 0; cc < 2; cc++) {
            int cch = (cc == 0) ? c0 : c1;
            int r = cch >> 2, part = cch & 3;
            {
                int m = m0 + r;
                int mm = (m < NN) ? m : (NN - 1);
                int kcat = kt + part * 8;
                const __half* p = (kcat < KH) ? (A + (size_t)mm * KH + kcat)
                                              : (H + (size_t)mm * KH + (kcat - KH));
                uint32_t d = (uint32_t)__cvta_generic_to_shared(&As[stg][r * AS_STR + part * 8]);
                cp16(d, p);
            }
            {
                const __half* p = W16 + (size_t)r * 256 + kt + part * 8;
                uint32_t d = (uint32_t)__cvta_generic_to_shared(&Bs[stg][r * BS_STR + part * 8]);
                cp16(d, p);
            }
        }
    };

    float c[2][8][4];
    #pragma unroll
    for (int mf = 0; mf < 2; mf++)
        #pragma unroll
        for (int nf = 0; nf < 8; nf++)
            #pragma unroll
            for (int j = 0; j < 4; j++) c[mf][nf][j] = 0.0f;

    issue(0, 0);
    CP_COMMIT();

    const int l7 = lane & 7;
    const int g = lane >> 3;
    const int aRowOff = (g & 1) * 8;
    const int aKOff   = (g & 2) * 4;
    const int bNOff   = (g & 2) * 4;
    const int bKOff   = (g & 1) * 8;

    #pragma unroll 1
    for (int it = 0; it < NIT; it++) {
        if (it + 1 < NIT) {
            issue((it + 1) & 1, (it + 1) * 32);
            CP_COMMIT();
            cp_wait<1>();
        } else {
            cp_wait<0>();
        }
        __syncthreads();

        const int stg = it & 1;
        const uint32_t aBase = (uint32_t)__cvta_generic_to_shared(&As[stg][0]);
        const uint32_t bBase = (uint32_t)__cvta_generic_to_shared(&Bs[stg][0]);

        #pragma unroll
        for (int s = 0; s < 2; s++) {
            const int kb = s * 16;
            uint32_t a[2][4];
            #pragma unroll
            for (int mf = 0; mf < 2; mf++) {
                int row = wm * 32 + mf * 16 + l7 + aRowOff;
                uint32_t addr = aBase + (uint32_t)(row * AS_STR + kb + aKOff) * 2;
                ldsm4(a[mf][0], a[mf][1], a[mf][2], a[mf][3], addr);
            }
            uint32_t bfr[8][2];
            #pragma unroll
            for (int p = 0; p < 4; p++) {
                int n = wn2 * 64 + p * 16 + l7 + bNOff;
                uint32_t addr = bBase + (uint32_t)(n * BS_STR + kb + bKOff) * 2;
                ldsm4(bfr[2 * p][0], bfr[2 * p][1], bfr[2 * p + 1][0], bfr[2 * p + 1][1], addr);
            }
            #pragma unroll
            for (int mf = 0; mf < 2; mf++) {
                #pragma unroll
                for (int nf = 0; nf < 8; nf++) {
                    asm volatile(
                        "mma.sync.aligned.m16n8k16.row.col.f32.f16.f16.f32 "
                        "{%0,%1,%2,%3}, {%4,%5,%6,%7}, {%8,%9}, {%0,%1,%2,%3};"
                        : "+f"(c[mf][nf][0]), "+f"(c[mf][nf][1]),
                          "+f"(c[mf][nf][2]), "+f"(c[mf][nf][3])
                        : "r"(a[mf][0]), "r"(a[mf][1]), "r"(a[mf][2]), "r"(a[mf][3]),
                          "r"(bfr[nf][0]), "r"(bfr[nf][1]));
                }
            }
        }
        __syncthreads();
    }

    // ---- epilogue: bias + activation + fp16 store ----
    const int colbase = wn2 * 64 + (lane & 3) * 2;
    float2 bb[8];
    #pragma unroll
    for (int nf = 0; nf < 8; nf++)
        bb[nf] = *(const float2*)(bias + colbase + nf * 8);

    #pragma unroll
    for (int mf = 0; mf < 2; mf++) {
        #pragma unroll
        for (int half = 0; half < 2; half++) {
            int m = m0 + wm * 32 + mf * 16 + (lane >> 2) + half * 8;
            if (m < NN) {
                __half* orow = Out + (size_t)m * CH;
                #pragma unroll
                for (int nf = 0; nf < 8; nf++) {
                    float vx = c[mf][nf][half * 2 + 0] + bb[nf].x;
                    float vy = c[mf][nf][half * 2 + 1] + bb[nf].y;
                    if (ACT == 1) {
                        vx = fmaxf(vx, 0.f);
                        vy = fmaxf(vy, 0.f);
                    } else if (ACT == 2) {
                        vx = (vx > 0.f) ? vx : NEG_SLOPE * vx;
                        vy = (vy > 0.f) ? vy : NEG_SLOPE * vy;
                    }
                    *(__half2*)(orow + colbase + nf * 8) = __floats2half2_rn(vx, vy);
                }
            }
        }
    }
}

// ---------------------------------------------------------------------------
// Fused segment-mean pool + linear head: one block per graph (batch sorted).
// ---------------------------------------------------------------------------
__global__ void k_poolhead(const __half* __restrict__ h,
                           const float* __restrict__ hW, const float* __restrict__ hb,
                           float* __restrict__ out) {
    const int g = blockIdx.x;
    const int t = threadIdx.x;
    const int s = g_gstart[g], e = g_gstart[g + 1];
    float acc = 0.f;
    for (int i = s; i < e; i++)
        acc += __half2float(h[(size_t)i * CH + t]);
    const float iv = 1.0f / (float)max(e - s, 1);
    const float p = acc * iv;
    __shared__ float r0[128], r1[128];
    r0[t] = p * hW[t * 2 + 0];
    r1[t] = p * hW[t * 2 + 1];
    __syncthreads();
    #pragma unroll
    for (int o = 64; o > 0; o >>= 1) {
        if (t < o) { r0[t] += r0[t + o]; r1[t] += r1[t + o]; }
        __syncthreads();
    }
    if (t == 0) {
        out[g * 2 + 0] = r0[0] + hb[0];
        out[g * 2 + 1] = r1[0] + hb[1];
    }
}

// ---------------------------------------------------------------------------
// Host launch: two-stream pipelined graph
// ---------------------------------------------------------------------------
static void* sym_addr(const void* sym) {
    void* p = nullptr;
    cudaGetSymbolAddress(&p, sym);
    return p;
}

extern "C" void kernel_launch(void* const* d_in, const int* in_sizes, int n_in,
                              void* d_out, int out_size) {
    const float* x    = (const float*)d_in[0];
    const int*   ei   = (const int*)d_in[1];
    const int*   srcp = ei;
    const int*   dstp = ei + EE;
    const int*   batch = (const int*)d_in[2];
    const float* Wl0 = (const float*)d_in[3];
    const float* Wr0 = (const float*)d_in[4];
    const float* b0  = (const float*)d_in[5];
    const float* Wl  = (const float*)d_in[6];
    const float* Wr  = (const float*)d_in[7];
    const float* bb  = (const float*)d_in[8];
    const float* hW  = (const float*)d_in[9];
    const float* hb  = (const float*)d_in[10];
    float* out = (float*)d_out;

    __half* h16A  = (__half*)sym_addr(g_h16A);
    __half* h16B  = (__half*)sym_addr(g_h16B);
    __half* agg16 = (__half*)sym_addr(g_agg16);
    __half* x16   = (__half*)sym_addr(g_x16);
    __half* W16   = (__half*)sym_addr(g_W16);
    int*    deg   = (int*)sym_addr(g_deg);

    // Side stream + events, created once (first call is the non-captured
    // correctness run; captured calls reuse them).
    static cudaStream_t s1 = nullptr;
    static cudaEvent_t evFork, evPrep, evA1[12], evA2[12], evG2[12];
    if (!s1) {
        cudaStreamCreateWithFlags(&s1, cudaStreamNonBlocking);
        cudaEventCreateWithFlags(&evFork, cudaEventDisableTiming);
        cudaEventCreateWithFlags(&evPrep, cudaEventDisableTiming);
        for (int i = 0; i < 12; i++) {
            cudaEventCreateWithFlags(&evA1[i], cudaEventDisableTiming);
            cudaEventCreateWithFlags(&evA2[i], cudaEventDisableTiming);
            cudaEventCreateWithFlags(&evG2[i], cudaEventDisableTiming);
        }
    }

    const int TPB = 256;
    const int aggB0 = (NSPLIT * 32 + TPB - 1) / TPB;
    const int aggB1 = ((NN - NSPLIT) * 32 + TPB - 1) / TPB;

    // ---- fork side stream ----
    k_zero_i<<<(NN + TPB - 1) / TPB, TPB>>>(deg, NN);
    cudaEventRecord(evFork, 0);
    cudaStreamWaitEvent(s1, evFork, 0);

    // side stream: prep (x16, W16, gstart) — independent of CSR chain
    k_prep2<<<(NN * CIN + TPB - 1) / TPB, TPB, 0, s1>>>(x, batch, Wl0, Wr0, Wl, Wr);
    cudaEventRecord(evPrep, s1);

    // main stream: CSR chain
    k_count<<<(EE + TPB - 1) / TPB, TPB>>>(dstp);
    k_scan2<<<1, 1024>>>();
    k_fill<<<(EE + TPB - 1) / TPB, TPB>>>(srcp, dstp);
    cudaStreamWaitEvent(0, evPrep, 0);   // agg needs x16; gemm needs W16 (s1-serial)

    // ---- layers: agg slices on main, gemm slices on s1 ----
    __half* hcur = (__half*)x16;  // layer 0 input
    __half* houtA = h16A;
    __half* houtB = h16B;

    for (int ci = 0; ci < 12; ci++) {
        __half* hout = (ci & 1) ? houtB : houtA;
        const __half* wt = W16 + (size_t)ci * 128 * 256;
        const float* bi = (ci == 0) ? b0 : (bb + (size_t)(ci - 1) * CH);
        int act = (ci == 11) ? 0 : ((ci == 3 || ci == 7) ? 2 : 1);

        if (ci > 0) cudaStreamWaitEvent(0, evG2[ci - 1], 0);  // hcur complete

        if (ci == 0) {
            k_agg16<64><<<aggB0, TPB>>>(hcur, agg16, 0, NSPLIT);
            cudaEventRecord(evA1[ci], 0);
            k_agg16<64><<<aggB1, TPB>>>(hcur, agg16, NSPLIT, NN);
            cudaEventRecord(evA2[ci], 0);
            cudaStreamWaitEvent(s1, evA1[ci], 0);
            k_gemm16<64, 1><<<TILES0, TPB, 0, s1>>>(agg16, hcur, wt, bi, hout, 0);
            cudaStreamWaitEvent(s1, evA2[ci], 0);
            k_gemm16<64, 1><<<TILES1, TPB, 0, s1>>>(agg16, hcur, wt, bi, hout, TILES0);
        } else {
            k_agg16<128><<<aggB0, TPB>>>(hcur, agg16, 0, NSPLIT);
            cudaEventRecord(evA1[ci], 0);
            k_agg16<128><<<aggB1, TPB>>>(hcur, agg16, NSPLIT, NN);
            cudaEventRecord(evA2[ci], 0);
            cudaStreamWaitEvent(s1, evA1[ci], 0);
            if (act == 0) {
                k_gemm16<128, 0><<<TILES0, TPB, 0, s1>>>(agg16, hcur, wt, bi, hout, 0);
                cudaStreamWaitEvent(s1, evA2[ci], 0);
                k_gemm16<128, 0><<<TILES1, TPB, 0, s1>>>(agg16, hcur, wt, bi, hout, TILES0);
            } else if (act == 2) {
                k_gemm16<128, 2><<<TILES0, TPB, 0, s1>>>(agg16, hcur, wt, bi, hout, 0);
                cudaStreamWaitEvent(s1, evA2[ci], 0);
                k_gemm16<128, 2><<<TILES1, TPB, 0, s1>>>(agg16, hcur, wt, bi, hout, TILES0);
            } else {
                k_gemm16<128, 1><<<TILES0, TPB, 0, s1>>>(agg16, hcur, wt, bi, hout, 0);
                cudaStreamWaitEvent(s1, evA2[ci], 0);
                k_gemm16<128, 1><<<TILES1, TPB, 0, s1>>>(agg16, hcur, wt, bi, hout, TILES0);
            }
        }
        cudaEventRecord(evG2[ci], s1);
        hcur = hout;
    }

    // ---- join + fused global mean pool + head ----
    cudaStreamWaitEvent(0, evG2[11], 0);
    k_poolhead<<<GG, 128>>>(hcur, hW, hb, out);
}

// round 14
// speedup vs baseline: 1.9248x; 1.2440x over previous
#include <cuda_runtime.h>
#include <cuda_fp16.h>
#include <cstddef>
#include <cstdint>

// Problem constants (fixed by the dataset)
#define NN   50000
#define EE   800000
#define GG   512
#define CH   128
#define CIN  64
#define NEG_SLOPE 0.01f

#define TILE_M 128
#define GEMM_BLOCKS ((NN + TILE_M - 1) / TILE_M)   // 391

// ---------------------------------------------------------------------------
// Device-global scratch
// ---------------------------------------------------------------------------
__device__ __half g_h16A[NN * CH];
__device__ __half g_h16B[NN * CH];
__device__ __half g_agg16[NN * CH];
__device__ __half g_x16[NN * CIN];
__device__ __half g_W16[12 * 128 * 256];   // [layer][n=128][k=256]
__device__ int   g_deg[NN];
__device__ int   g_rowptr[NN + 1];
__device__ int   g_cursor[NN];
__device__ int   g_col[EE];
__device__ int   g_gstart[GG + 1];

// ---------------------------------------------------------------------------
// Prep: zero deg, cvt x->fp16, build W16 table, graph bounds.
// ---------------------------------------------------------------------------
__global__ void k_prep(const float* __restrict__ x, const int* __restrict__ batch,
                       const float* __restrict__ Wl0, const float* __restrict__ Wr0,
                       const float* __restrict__ Wl, const float* __restrict__ Wr) {
    int i = blockIdx.x * blockDim.x + threadIdx.x;
    if (i < NN * CIN) g_x16[i] = __float2half_rn(x[i]);
    if (i < 12 * 128 * 256) {
        int l = i >> 15;
        int n = (i >> 8) & 127;
        int k = i & 255;
        float v = 0.0f;
        if (l == 0) {
            if (k < 64)       v = Wl0[k * 128 + n];
            else if (k < 128) v = Wr0[(k - 64) * 128 + n];
        } else {
            int li = l - 1;
            if (k < 128) v = Wl[(size_t)li * 128 * 128 + k * 128 + n];
            else         v = Wr[(size_t)li * 128 * 128 + (k - 128) * 128 + n];
        }
        g_W16[i] = __float2half_rn(v);
    }
    if (i < NN) g_deg[i] = 0;
    if (i <= GG) {
        int lo = 0, hi = NN;
        while (lo < hi) {
            int mid = (lo + hi) >> 1;
            if (batch[mid] < i) lo = mid + 1; else hi = mid;
        }
        g_gstart[i] = lo;
    }
}

__global__ void k_count(const int* __restrict__ dst) {
    int i = blockIdx.x * blockDim.x + threadIdx.x;
    if (i < EE) atomicAdd(&g_deg[dst[i]], 1);
}

// ---------------------------------------------------------------------------
// Two-pass vectorized single-block scan (register-safe).
// Thread t owns 13 int4 chunks (52 elems). Pass 1: independent-sum streams.
// Block shuffle-scan of per-thread sums. Pass 2: reload (L2-hot) + write
// prefixed rowptr/cursor as int4.
// NN = 50000 = 12500 int4s. 1024 threads * 13 = 13312 >= 12500.
// ---------------------------------------------------------------------------
#define SCAN_NQ 13
__global__ __launch_bounds__(1024) void k_scan3() {
    const int tid = threadIdx.x;
    const int q0 = tid * SCAN_NQ;
    const int4* dp = (const int4*)g_deg;

    // ---- pass 1: sum with 4 independent accumulators (high MLP) ----
    int s0 = 0, s1 = 0, s2 = 0, s3 = 0;
    #pragma unroll
    for (int j = 0; j < SCAN_NQ; j++) {
        int q = q0 + j;
        if (q < NN / 4) {
            int4 v = dp[q];
            s0 += v.x; s1 += v.y; s2 += v.z; s3 += v.w;
        }
    }
    const int sum = s0 + s1 + s2 + s3;

    // ---- block exclusive scan of per-thread sums ----
    const int lane = tid & 31, w = tid >> 5;
    int s = sum;
    #pragma unroll
    for (int o = 1; o < 32; o <<= 1) {
        int t = __shfl_up_sync(0xffffffffu, s, o);
        if (lane >= o) s += t;
    }
    __shared__ int wsum[32];
    if (lane == 31) wsum[w] = s;
    __syncthreads();
    if (w == 0) {
        int ws = wsum[lane];
        #pragma unroll
        for (int o = 1; o < 32; o <<= 1) {
            int t = __shfl_up_sync(0xffffffffu, ws, o);
            if (lane >= o) ws += t;
        }
        wsum[lane] = ws;
    }
    __syncthreads();
    int run = s - sum + (w > 0 ? wsum[w - 1] : 0);  // exclusive prefix

    // ---- pass 2: reload (L2-hot) and write prefix vectors ----
    int4* rp = (int4*)g_rowptr;
    int4* cp = (int4*)g_cursor;
    #pragma unroll
    for (int j = 0; j < SCAN_NQ; j++) {
        int q = q0 + j;
        if (q < NN / 4) {
            int4 v = dp[q];
            int4 o;
            o.x = run;
            o.y = run + v.x;
            o.z = o.y + v.y;
            o.w = o.z + v.z;
            run = o.w + v.w;
            rp[q] = o;
            cp[q] = o;
        }
    }
    if (tid == 1023) g_rowptr[NN] = run;  // last thread's run == grand total
}

__global__ void k_fill(const int* __restrict__ src, const int* __restrict__ dst) {
    int i = blockIdx.x * blockDim.x + threadIdx.x;
    if (i < EE) {
        int d = dst[i];
        int pos = atomicAdd(&g_cursor[d], 1);
        g_col[pos] = src[i];
    }
}

// ---------------------------------------------------------------------------
// Mean aggregation (fp16 in/out, fp32 accumulate): one warp per node.
// inv_deg computed from rowptr (no g_inv array).
// ---------------------------------------------------------------------------
template <int C>
__global__ void k_agg16(const __half* __restrict__ h, __half* __restrict__ agg) {
    int gw = (blockIdx.x * blockDim.x + threadIdx.x) >> 5;
    if (gw >= NN) return;
    int lane = threadIdx.x & 31;
    int b = g_rowptr[gw], e = g_rowptr[gw + 1];
    float iv = 1.0f / (float)max(e - b, 1);
    if constexpr (C == 128) {
        const uint2* hp = (const uint2*)h;
        float4 a0 = make_float4(0.f, 0.f, 0.f, 0.f);
        float4 a1 = make_float4(0.f, 0.f, 0.f, 0.f);
        int j = b;
        for (; j + 1 < e; j += 2) {
            int s0 = g_col[j], s1 = g_col[j + 1];
            uint2 u0 = hp[s0 * 32 + lane];
            uint2 u1 = hp[s1 * 32 + lane];
            float2 p0 = __half22float2(*(const __half2*)&u0.x);
            float2 q0 = __half22float2(*(const __half2*)&u0.y);
            float2 p1 = __half22float2(*(const __half2*)&u1.x);
            float2 q1 = __half22float2(*(const __half2*)&u1.y);
            a0.x += p0.x; a0.y += p0.y; a0.z += q0.x; a0.w += q0.y;
            a1.x += p1.x; a1.y += p1.y; a1.z += q1.x; a1.w += q1.y;
        }
        if (j < e) {
            int s0 = g_col[j];
            uint2 u0 = hp[s0 * 32 + lane];
            float2 p0 = __half22float2(*(const __half2*)&u0.x);
            float2 q0 = __half22float2(*(const __half2*)&u0.y);
            a0.x += p0.x; a0.y += p0.y; a0.z += q0.x; a0.w += q0.y;
        }
        a0.x = (a0.x + a1.x) * iv; a0.y = (a0.y + a1.y) * iv;
        a0.z = (a0.z + a1.z) * iv; a0.w = (a0.w + a1.w) * iv;
        uint2 o;
        *(__half2*)&o.x = __floats2half2_rn(a0.x, a0.y);
        *(__half2*)&o.y = __floats2half2_rn(a0.z, a0.w);
        ((uint2*)agg)[gw * 32 + lane] = o;
    } else {  // C == 64
        const uint32_t* hp = (const uint32_t*)h;
        float2 a0 = make_float2(0.f, 0.f), a1 = make_float2(0.f, 0.f);
        int j = b;
        for (; j + 1 < e; j += 2) {
            int s0 = g_col[j], s1 = g_col[j + 1];
            uint32_t u0 = hp[s0 * 32 + lane];
            uint32_t u1 = hp[s1 * 32 + lane];
            float2 p0 = __half22float2(*(const __half2*)&u0);
            float2 p1 = __half22float2(*(const __half2*)&u1);
            a0.x += p0.x; a0.y += p0.y;
            a1.x += p1.x; a1.y += p1.y;
        }
        if (j < e) {
            uint32_t u0 = hp[g_col[j] * 32 + lane];
            float2 p0 = __half22float2(*(const __half2*)&u0);
            a0.x += p0.x; a0.y += p0.y;
        }
        a0.x = (a0.x + a1.x) * iv; a0.y = (a0.y + a1.y) * iv;
        uint32_t o;
        *(__half2*)&o = __floats2half2_rn(a0.x, a0.y);
        ((uint32_t*)agg)[gw * 32 + lane] = o;
    }
}

// ---------------------------------------------------------------------------
// fp16 mma.sync GEMM, cp.async double-buffered, ldmatrix fragment loads.
// ---------------------------------------------------------------------------
#define AS_STR 40
#define BS_STR 40

__device__ __forceinline__ void cp16(uint32_t dst, const void* src) {
    asm volatile("cp.async.ca.shared.global [%0], [%1], 16;" :: "r"(dst), "l"(src));
}
#define CP_COMMIT() asm volatile("cp.async.commit_group;" ::: "memory")
template <int Nw>
__device__ __forceinline__ void cp_wait() {
    asm volatile("cp.async.wait_group %0;" :: "n"(Nw) : "memory");
}
__device__ __forceinline__ void ldsm4(uint32_t& r0, uint32_t& r1, uint32_t& r2,
                                      uint32_t& r3, uint32_t addr) {
    asm volatile("ldmatrix.sync.aligned.m8n8.x4.shared.b16 {%0,%1,%2,%3}, [%4];"
                 : "=r"(r0), "=r"(r1), "=r"(r2), "=r"(r3) : "r"(addr));
}

template <int KH, int ACT>
__global__ __launch_bounds__(256) void k_gemm16(
    const __half* __restrict__ A,    // aggregated fp16, [NN][KH]
    const __half* __restrict__ H,    // node features fp16, [NN][KH]
    const __half* __restrict__ W16,  // [128][256] transposed fp16 weights (layer)
    const float* __restrict__ bias,  // [128]
    __half* __restrict__ Out)        // [NN][128]
{
    constexpr int KT = 2 * KH;
    constexpr int NIT = KT / 32;
    __shared__ __half As[2][128 * AS_STR];
    __shared__ __half Bs[2][128 * BS_STR];

    const int tid = threadIdx.x;
    const int wid = tid >> 5;
    const int lane = tid & 31;
    const int wm = wid & 3;
    const int wn2 = wid >> 2;
    const int m0 = blockIdx.x * TILE_M;

    const int c0 = tid, c1 = tid + 256;

    auto issue = [&](int stg, int kt) {
        #pragma unroll
        for (int cc = 0; cc < 2; cc++) {
            int cch = (cc == 0) ? c0 : c1;
            int r = cch >> 2, part = cch & 3;
            {
                int m = m0 + r;
                int mm = (m < NN) ? m : (NN - 1);
                int kcat = kt + part * 8;
                const __half* p = (kcat < KH) ? (A + (size_t)mm * KH + kcat)
                                              : (H + (size_t)mm * KH + (kcat - KH));
                uint32_t d = (uint32_t)__cvta_generic_to_shared(&As[stg][r * AS_STR + part * 8]);
                cp16(d, p);
            }
            {
                const __half* p = W16 + (size_t)r * 256 + kt + part * 8;
                uint32_t d = (uint32_t)__cvta_generic_to_shared(&Bs[stg][r * BS_STR + part * 8]);
                cp16(d, p);
            }
        }
    };

    float c[2][8][4];
    #pragma unroll
    for (int mf = 0; mf < 2; mf++)
        #pragma unroll
        for (int nf = 0; nf < 8; nf++)
            #pragma unroll
            for (int j = 0; j < 4; j++) c[mf][nf][j] = 0.0f;

    issue(0, 0);
    CP_COMMIT();

    const int l7 = lane & 7;
    const int g = lane >> 3;
    const int aRowOff = (g & 1) * 8;
    const int aKOff   = (g & 2) * 4;
    const int bNOff   = (g & 2) * 4;
    const int bKOff   = (g & 1) * 8;

    #pragma unroll 1
    for (int it = 0; it < NIT; it++) {
        if (it + 1 < NIT) {
            issue((it + 1) & 1, (it + 1) * 32);
            CP_COMMIT();
            cp_wait<1>();
        } else {
            cp_wait<0>();
        }
        __syncthreads();

        const int stg = it & 1;
        const uint32_t aBase = (uint32_t)__cvta_generic_to_shared(&As[stg][0]);
        const uint32_t bBase = (uint32_t)__cvta_generic_to_shared(&Bs[stg][0]);

        #pragma unroll
        for (int s = 0; s < 2; s++) {
            const int kb = s * 16;
            uint32_t a[2][4];
            #pragma unroll
            for (int mf = 0; mf < 2; mf++) {
                int row = wm * 32 + mf * 16 + l7 + aRowOff;
                uint32_t addr = aBase + (uint32_t)(row * AS_STR + kb + aKOff) * 2;
                ldsm4(a[mf][0], a[mf][1], a[mf][2], a[mf][3], addr);
            }
            uint32_t bfr[8][2];
            #pragma unroll
            for (int p = 0; p < 4; p++) {
                int n = wn2 * 64 + p * 16 + l7 + bNOff;
                uint32_t addr = bBase + (uint32_t)(n * BS_STR + kb + bKOff) * 2;
                ldsm4(bfr[2 * p][0], bfr[2 * p][1], bfr[2 * p + 1][0], bfr[2 * p + 1][1], addr);
            }
            #pragma unroll
            for (int mf = 0; mf < 2; mf++) {
                #pragma unroll
                for (int nf = 0; nf < 8; nf++) {
                    asm volatile(
                        "mma.sync.aligned.m16n8k16.row.col.f32.f16.f16.f32 "
                        "{%0,%1,%2,%3}, {%4,%5,%6,%7}, {%8,%9}, {%0,%1,%2,%3};"
                        : "+f"(c[mf][nf][0]), "+f"(c[mf][nf][1]),
                          "+f"(c[mf][nf][2]), "+f"(c[mf][nf][3])
                        : "r"(a[mf][0]), "r"(a[mf][1]), "r"(a[mf][2]), "r"(a[mf][3]),
                          "r"(bfr[nf][0]), "r"(bfr[nf][1]));
                }
            }
        }
        __syncthreads();
    }

    // ---- epilogue: bias + activation + fp16 store ----
    const int colbase = wn2 * 64 + (lane & 3) * 2;
    float2 bb[8];
    #pragma unroll
    for (int nf = 0; nf < 8; nf++)
        bb[nf] = *(const float2*)(bias + colbase + nf * 8);

    #pragma unroll
    for (int mf = 0; mf < 2; mf++) {
        #pragma unroll
        for (int half = 0; half < 2; half++) {
            int m = m0 + wm * 32 + mf * 16 + (lane >> 2) + half * 8;
            if (m < NN) {
                __half* orow = Out + (size_t)m * CH;
                #pragma unroll
                for (int nf = 0; nf < 8; nf++) {
                    float vx = c[mf][nf][half * 2 + 0] + bb[nf].x;
                    float vy = c[mf][nf][half * 2 + 1] + bb[nf].y;
                    if (ACT == 1) {
                        vx = fmaxf(vx, 0.f);
                        vy = fmaxf(vy, 0.f);
                    } else if (ACT == 2) {
                        vx = (vx > 0.f) ? vx : NEG_SLOPE * vx;
                        vy = (vy > 0.f) ? vy : NEG_SLOPE * vy;
                    }
                    *(__half2*)(orow + colbase + nf * 8) = __floats2half2_rn(vx, vy);
                }
            }
        }
    }
}

// ---------------------------------------------------------------------------
// Fused segment-mean pool + linear head: one block per graph (batch sorted).
// ---------------------------------------------------------------------------
__global__ void k_poolhead(const __half* __restrict__ h,
                           const float* __restrict__ hW, const float* __restrict__ hb,
                           float* __restrict__ out) {
    const int g = blockIdx.x;
    const int t = threadIdx.x;
    const int s = g_gstart[g], e = g_gstart[g + 1];
    float acc = 0.f;
    for (int i = s; i < e; i++)
        acc += __half2float(h[(size_t)i * CH + t]);
    const float iv = 1.0f / (float)max(e - s, 1);
    const float p = acc * iv;
    __shared__ float r0[128], r1[128];
    r0[t] = p * hW[t * 2 + 0];
    r1[t] = p * hW[t * 2 + 1];
    __syncthreads();
    #pragma unroll
    for (int o = 64; o > 0; o >>= 1) {
        if (t < o) { r0[t] += r0[t + o]; r1[t] += r1[t + o]; }
        __syncthreads();
    }
    if (t == 0) {
        out[g * 2 + 0] = r0[0] + hb[0];
        out[g * 2 + 1] = r1[0] + hb[1];
    }
}

// ---------------------------------------------------------------------------
// Host launch
// ---------------------------------------------------------------------------
static void* sym_addr(const void* sym) {
    void* p = nullptr;
    cudaGetSymbolAddress(&p, sym);
    return p;
}

extern "C" void kernel_launch(void* const* d_in, const int* in_sizes, int n_in,
                              void* d_out, int out_size) {
    const float* x    = (const float*)d_in[0];
    const int*   ei   = (const int*)d_in[1];
    const int*   srcp = ei;
    const int*   dstp = ei + EE;
    const int*   batch = (const int*)d_in[2];
    const float* Wl0 = (const float*)d_in[3];
    const float* Wr0 = (const float*)d_in[4];
    const float* b0  = (const float*)d_in[5];
    const float* Wl  = (const float*)d_in[6];
    const float* Wr  = (const float*)d_in[7];
    const float* bb  = (const float*)d_in[8];
    const float* hW  = (const float*)d_in[9];
    const float* hb  = (const float*)d_in[10];
    float* out = (float*)d_out;

    __half* h16A  = (__half*)sym_addr(g_h16A);
    __half* h16B  = (__half*)sym_addr(g_h16B);
    __half* agg16 = (__half*)sym_addr(g_agg16);
    __half* x16   = (__half*)sym_addr(g_x16);
    __half* W16   = (__half*)sym_addr(g_W16);

    const int TPB = 256;

    // --- setup: prep (zero deg + cvt + W16 + gstart) -> count -> scan -> fill
    k_prep<<<(NN * CIN + TPB - 1) / TPB, TPB>>>(x, batch, Wl0, Wr0, Wl, Wr);
    k_count<<<(EE + TPB - 1) / TPB, TPB>>>(dstp);
    k_scan3<<<1, 1024>>>();
    k_fill<<<(EE + TPB - 1) / TPB, TPB>>>(srcp, dstp);

    const int aggBlocks = (NN * 32 + TPB - 1) / TPB;

    // --- conv 0 (C_IN=64 -> 128), ReLU ---
    k_agg16<64><<<aggBlocks, TPB>>>(x16, agg16);
    k_gemm16<64, 1><<<GEMM_BLOCKS, TPB>>>(agg16, x16, W16, b0, h16A);

    // --- convs 1..11 ---
    __half* hcur = h16A;
    __half* hnxt = h16B;
    for (int i = 0; i < 11; i++) {
        int ci = i + 1;
        k_agg16<128><<<aggBlocks, TPB>>>(hcur, agg16);
        const __half* wt = W16 + (size_t)(i + 1) * 128 * 256;
        const float* bi = bb + (size_t)i * CH;
        if (ci == 11) {
            k_gemm16<128, 0><<<GEMM_BLOCKS, TPB>>>(agg16, hcur, wt, bi, hnxt);
        } else if (ci == 3 || ci == 7) {
            k_gemm16<128, 2><<<GEMM_BLOCKS, TPB>>>(agg16, hcur, wt, bi, hnxt);
        } else {
            k_gemm16<128, 1><<<GEMM_BLOCKS, TPB>>>(agg16, hcur, wt, bi, hnxt);
        }
        __half* t = hcur; hcur = hnxt; hnxt = t;
    }

    // --- fused global mean pool + head ---
    k_poolhead<<<GG, 128>>>(hcur, hW, hb, out);
}

// round 15
// speedup vs baseline: 1.9784x; 1.0278x over previous
#include <cuda_runtime.h>
#include <cuda_fp16.h>
#include <cstddef>
#include <cstdint>

// Problem constants (fixed by the dataset)
#define NN   50000
#define EE   800000
#define GG   512
#define CH   128
#define CIN  64
#define NEG_SLOPE 0.01f

#define TILE_M 128
#define GEMM_BLOCKS ((NN + TILE_M - 1) / TILE_M)   // 391

// ---------------------------------------------------------------------------
// Device-global scratch
// ---------------------------------------------------------------------------
__device__ __half g_h16A[NN * CH];
__device__ __half g_h16B[NN * CH];
__device__ __half g_agg16[NN * CH];
__device__ __half g_x16[NN * CIN];
__device__ __half g_W16[12 * 128 * 256];   // [layer][n=128][k=256]
__device__ int   g_deg[NN];
__device__ int   g_rowptr[NN + 1];
__device__ int   g_cursor[NN];
__device__ int   g_col[EE];
__device__ int   g_gstart[GG + 1];

// ---------------------------------------------------------------------------
// Prep: zero deg, cvt x->fp16, build W16 table, graph bounds.
// ---------------------------------------------------------------------------
__global__ void k_prep(const float* __restrict__ x, const int* __restrict__ batch,
                       const float* __restrict__ Wl0, const float* __restrict__ Wr0,
                       const float* __restrict__ Wl, const float* __restrict__ Wr) {
    int i = blockIdx.x * blockDim.x + threadIdx.x;
    if (i < NN * CIN) g_x16[i] = __float2half_rn(x[i]);
    if (i < 12 * 128 * 256) {
        int l = i >> 15;
        int n = (i >> 8) & 127;
        int k = i & 255;
        float v = 0.0f;
        if (l == 0) {
            if (k < 64)       v = Wl0[k * 128 + n];
            else if (k < 128) v = Wr0[(k - 64) * 128 + n];
        } else {
            int li = l - 1;
            if (k < 128) v = Wl[(size_t)li * 128 * 128 + k * 128 + n];
            else         v = Wr[(size_t)li * 128 * 128 + (k - 128) * 128 + n];
        }
        g_W16[i] = __float2half_rn(v);
    }
    if (i < NN) g_deg[i] = 0;
    if (i <= GG) {
        int lo = 0, hi = NN;
        while (lo < hi) {
            int mid = (lo + hi) >> 1;
            if (batch[mid] < i) lo = mid + 1; else hi = mid;
        }
        g_gstart[i] = lo;
    }
}

__global__ void k_count(const int* __restrict__ dst) {
    int i = blockIdx.x * blockDim.x + threadIdx.x;
    if (i < EE) atomicAdd(&g_deg[dst[i]], 1);
}

// ---------------------------------------------------------------------------
// Two-pass vectorized single-block scan (register-safe).
// ---------------------------------------------------------------------------
#define SCAN_NQ 13
__global__ __launch_bounds__(1024) void k_scan3() {
    const int tid = threadIdx.x;
    const int q0 = tid * SCAN_NQ;
    const int4* dp = (const int4*)g_deg;

    int s0 = 0, s1 = 0, s2 = 0, s3 = 0;
    #pragma unroll
    for (int j = 0; j < SCAN_NQ; j++) {
        int q = q0 + j;
        if (q < NN / 4) {
            int4 v = dp[q];
            s0 += v.x; s1 += v.y; s2 += v.z; s3 += v.w;
        }
    }
    const int sum = s0 + s1 + s2 + s3;

    const int lane = tid & 31, w = tid >> 5;
    int s = sum;
    #pragma unroll
    for (int o = 1; o < 32; o <<= 1) {
        int t = __shfl_up_sync(0xffffffffu, s, o);
        if (lane >= o) s += t;
    }
    __shared__ int wsum[32];
    if (lane == 31) wsum[w] = s;
    __syncthreads();
    if (w == 0) {
        int ws = wsum[lane];
        #pragma unroll
        for (int o = 1; o < 32; o <<= 1) {
            int t = __shfl_up_sync(0xffffffffu, ws, o);
            if (lane >= o) ws += t;
        }
        wsum[lane] = ws;
    }
    __syncthreads();
    int run = s - sum + (w > 0 ? wsum[w - 1] : 0);

    int4* rp = (int4*)g_rowptr;
    int4* cp = (int4*)g_cursor;
    #pragma unroll
    for (int j = 0; j < SCAN_NQ; j++) {
        int q = q0 + j;
        if (q < NN / 4) {
            int4 v = dp[q];
            int4 o;
            o.x = run;
            o.y = run + v.x;
            o.z = o.y + v.y;
            o.w = o.z + v.z;
            run = o.w + v.w;
            rp[q] = o;
            cp[q] = o;
        }
    }
    if (tid == 1023) g_rowptr[NN] = run;
}

__global__ void k_fill(const int* __restrict__ src, const int* __restrict__ dst) {
    int i = blockIdx.x * blockDim.x + threadIdx.x;
    if (i < EE) {
        int d = dst[i];
        int pos = atomicAdd(&g_cursor[d], 1);
        g_col[pos] = src[i];
    }
}

// ---------------------------------------------------------------------------
// Mean aggregation (fp16 in/out, fp32 accumulate): one warp per node.
// ---------------------------------------------------------------------------
template <int C>
__global__ void k_agg16(const __half* __restrict__ h, __half* __restrict__ agg) {
    int gw = (blockIdx.x * blockDim.x + threadIdx.x) >> 5;
    if (gw >= NN) return;
    int lane = threadIdx.x & 31;
    int b = g_rowptr[gw], e = g_rowptr[gw + 1];
    float iv = 1.0f / (float)max(e - b, 1);
    if constexpr (C == 128) {
        const uint2* hp = (const uint2*)h;
        float4 a0 = make_float4(0.f, 0.f, 0.f, 0.f);
        float4 a1 = make_float4(0.f, 0.f, 0.f, 0.f);
        int j = b;
        for (; j + 1 < e; j += 2) {
            int s0 = g_col[j], s1 = g_col[j + 1];
            uint2 u0 = hp[s0 * 32 + lane];
            uint2 u1 = hp[s1 * 32 + lane];
            float2 p0 = __half22float2(*(const __half2*)&u0.x);
            float2 q0 = __half22float2(*(const __half2*)&u0.y);
            float2 p1 = __half22float2(*(const __half2*)&u1.x);
            float2 q1 = __half22float2(*(const __half2*)&u1.y);
            a0.x += p0.x; a0.y += p0.y; a0.z += q0.x; a0.w += q0.y;
            a1.x += p1.x; a1.y += p1.y; a1.z += q1.x; a1.w += q1.y;
        }
        if (j < e) {
            int s0 = g_col[j];
            uint2 u0 = hp[s0 * 32 + lane];
            float2 p0 = __half22float2(*(const __half2*)&u0.x);
            float2 q0 = __half22float2(*(const __half2*)&u0.y);
            a0.x += p0.x; a0.y += p0.y; a0.z += q0.x; a0.w += q0.y;
        }
        a0.x = (a0.x + a1.x) * iv; a0.y = (a0.y + a1.y) * iv;
        a0.z = (a0.z + a1.z) * iv; a0.w = (a0.w + a1.w) * iv;
        uint2 o;
        *(__half2*)&o.x = __floats2half2_rn(a0.x, a0.y);
        *(__half2*)&o.y = __floats2half2_rn(a0.z, a0.w);
        ((uint2*)agg)[gw * 32 + lane] = o;
    } else {  // C == 64
        const uint32_t* hp = (const uint32_t*)h;
        float2 a0 = make_float2(0.f, 0.f), a1 = make_float2(0.f, 0.f);
        int j = b;
        for (; j + 1 < e; j += 2) {
            int s0 = g_col[j], s1 = g_col[j + 1];
            uint32_t u0 = hp[s0 * 32 + lane];
            uint32_t u1 = hp[s1 * 32 + lane];
            float2 p0 = __half22float2(*(const __half2*)&u0);
            float2 p1 = __half22float2(*(const __half2*)&u1);
            a0.x += p0.x; a0.y += p0.y;
            a1.x += p1.x; a1.y += p1.y;
        }
        if (j < e) {
            uint32_t u0 = hp[g_col[j] * 32 + lane];
            float2 p0 = __half22float2(*(const __half2*)&u0);
            a0.x += p0.x; a0.y += p0.y;
        }
        a0.x = (a0.x + a1.x) * iv; a0.y = (a0.y + a1.y) * iv;
        uint32_t o;
        *(__half2*)&o = __floats2half2_rn(a0.x, a0.y);
        ((uint32_t*)agg)[gw * 32 + lane] = o;
    }
}

// ---------------------------------------------------------------------------
// fp16 mma.sync GEMM, 3-stage cp.async pipeline (ONE barrier per k-iter),
// ldmatrix fragment loads. Dynamic smem: 3 stages x (As + Bs).
// ---------------------------------------------------------------------------
#define AS_STR 40
#define BS_STR 40
#define STG_HALVES (128 * AS_STR + 128 * BS_STR)
#define SMEM_GEMM (3 * STG_HALVES * 2)

__device__ __forceinline__ void cp16(uint32_t dst, const void* src) {
    asm volatile("cp.async.ca.shared.global [%0], [%1], 16;" :: "r"(dst), "l"(src));
}
#define CP_COMMIT() asm volatile("cp.async.commit_group;" ::: "memory")
template <int Nw>
__device__ __forceinline__ void cp_wait() {
    asm volatile("cp.async.wait_group %0;" :: "n"(Nw) : "memory");
}
__device__ __forceinline__ void ldsm4(uint32_t& r0, uint32_t& r1, uint32_t& r2,
                                      uint32_t& r3, uint32_t addr) {
    asm volatile("ldmatrix.sync.aligned.m8n8.x4.shared.b16 {%0,%1,%2,%3}, [%4];"
                 : "=r"(r0), "=r"(r1), "=r"(r2), "=r"(r3) : "r"(addr));
}

template <int KH, int ACT>
__global__ __launch_bounds__(256) void k_gemm16(
    const __half* __restrict__ A,    // aggregated fp16, [NN][KH]
    const __half* __restrict__ H,    // node features fp16, [NN][KH]
    const __half* __restrict__ W16,  // [128][256] transposed fp16 weights (layer)
    const float* __restrict__ bias,  // [128]
    __half* __restrict__ Out)        // [NN][128]
{
    constexpr int KT = 2 * KH;
    constexpr int NIT = KT / 32;
    extern __shared__ __half sm[];

    const int tid = threadIdx.x;
    const int wid = tid >> 5;
    const int lane = tid & 31;
    const int wm = wid & 3;
    const int wn2 = wid >> 2;
    const int m0 = blockIdx.x * TILE_M;

    const int c0 = tid, c1 = tid + 256;

    auto issue = [&](int stg, int kt) {
        __half* As = sm + stg * STG_HALVES;
        __half* Bs = As + 128 * AS_STR;
        #pragma unroll
        for (int cc = 0; cc < 2; cc++) {
            int cch = (cc == 0) ? c0 : c1;
            int r = cch >> 2, part = cch & 3;
            {
                int m = m0 + r;
                int mm = (m < NN) ? m : (NN - 1);
                int kcat = kt + part * 8;
                const __half* p = (kcat < KH) ? (A + (size_t)mm * KH + kcat)
                                              : (H + (size_t)mm * KH + (kcat - KH));
                uint32_t d = (uint32_t)__cvta_generic_to_shared(&As[r * AS_STR + part * 8]);
                cp16(d, p);
            }
            {
                const __half* p = W16 + (size_t)r * 256 + kt + part * 8;
                uint32_t d = (uint32_t)__cvta_generic_to_shared(&Bs[r * BS_STR + part * 8]);
                cp16(d, p);
            }
        }
    };

    float c[2][8][4];
    #pragma unroll
    for (int mf = 0; mf < 2; mf++)
        #pragma unroll
        for (int nf = 0; nf < 8; nf++)
            #pragma unroll
            for (int j = 0; j < 4; j++) c[mf][nf][j] = 0.0f;

    // prologue: issue stages 0, 1
    issue(0, 0);
    CP_COMMIT();
    issue(1, 32);
    CP_COMMIT();

    const int l7 = lane & 7;
    const int g = lane >> 3;
    const int aRowOff = (g & 1) * 8;
    const int aKOff   = (g & 2) * 4;
    const int bNOff   = (g & 2) * 4;
    const int bKOff   = (g & 1) * 8;

    int st = 0;  // stage of current iteration (it % 3)
    #pragma unroll 1
    for (int it = 0; it < NIT; it++) {
        // guarantee stage `it` landed: at most group it+1 outstanding
        if (it < NIT - 1) cp_wait<1>(); else cp_wait<0>();
        __syncthreads();   // all threads see stage `it`; all done computing it-1

        if (it + 2 < NIT) {
            int st2 = (st == 0) ? 2 : st - 1;   // (st+2)%3
            issue(st2, (it + 2) * 32);
            CP_COMMIT();
        }

        const __half* Asb = sm + st * STG_HALVES;
        const __half* Bsb = Asb + 128 * AS_STR;
        const uint32_t aBase = (uint32_t)__cvta_generic_to_shared(Asb);
        const uint32_t bBase = (uint32_t)__cvta_generic_to_shared(Bsb);

        #pragma unroll
        for (int s = 0; s < 2; s++) {
            const int kb = s * 16;
            uint32_t a[2][4];
            #pragma unroll
            for (int mf = 0; mf < 2; mf++) {
                int row = wm * 32 + mf * 16 + l7 + aRowOff;
                uint32_t addr = aBase + (uint32_t)(row * AS_STR + kb + aKOff) * 2;
                ldsm4(a[mf][0], a[mf][1], a[mf][2], a[mf][3], addr);
            }
            uint32_t bfr[8][2];
            #pragma unroll
            for (int p = 0; p < 4; p++) {
                int n = wn2 * 64 + p * 16 + l7 + bNOff;
                uint32_t addr = bBase + (uint32_t)(n * BS_STR + kb + bKOff) * 2;
                ldsm4(bfr[2 * p][0], bfr[2 * p][1], bfr[2 * p + 1][0], bfr[2 * p + 1][1], addr);
            }
            #pragma unroll
            for (int mf = 0; mf < 2; mf++) {
                #pragma unroll
                for (int nf = 0; nf < 8; nf++) {
                    asm volatile(
                        "mma.sync.aligned.m16n8k16.row.col.f32.f16.f16.f32 "
                        "{%0,%1,%2,%3}, {%4,%5,%6,%7}, {%8,%9}, {%0,%1,%2,%3};"
                        : "+f"(c[mf][nf][0]), "+f"(c[mf][nf][1]),
                          "+f"(c[mf][nf][2]), "+f"(c[mf][nf][3])
                        : "r"(a[mf][0]), "r"(a[mf][1]), "r"(a[mf][2]), "r"(a[mf][3]),
                          "r"(bfr[nf][0]), "r"(bfr[nf][1]));
                }
            }
        }
        st = (st == 2) ? 0 : st + 1;
    }

    // ---- epilogue: bias + activation + fp16 store ----
    const int colbase = wn2 * 64 + (lane & 3) * 2;
    float2 bb[8];
    #pragma unroll
    for (int nf = 0; nf < 8; nf++)
        bb[nf] = *(const float2*)(bias + colbase + nf * 8);

    #pragma unroll
    for (int mf = 0; mf < 2; mf++) {
        #pragma unroll
        for (int half = 0; half < 2; half++) {
            int m = m0 + wm * 32 + mf * 16 + (lane >> 2) + half * 8;
            if (m < NN) {
                __half* orow = Out + (size_t)m * CH;
                #pragma unroll
                for (int nf = 0; nf < 8; nf++) {
                    float vx = c[mf][nf][half * 2 + 0] + bb[nf].x;
                    float vy = c[mf][nf][half * 2 + 1] + bb[nf].y;
                    if (ACT == 1) {
                        vx = fmaxf(vx, 0.f);
                        vy = fmaxf(vy, 0.f);
                    } else if (ACT == 2) {
                        vx = (vx > 0.f) ? vx : NEG_SLOPE * vx;
                        vy = (vy > 0.f) ? vy : NEG_SLOPE * vy;
                    }
                    *(__half2*)(orow + colbase + nf * 8) = __floats2half2_rn(vx, vy);
                }
            }
        }
    }
}

// ---------------------------------------------------------------------------
// Fused segment-mean pool + linear head: one block per graph (batch sorted).
// ---------------------------------------------------------------------------
__global__ void k_poolhead(const __half* __restrict__ h,
                           const float* __restrict__ hW, const float* __restrict__ hb,
                           float* __restrict__ out) {
    const int g = blockIdx.x;
    const int t = threadIdx.x;
    const int s = g_gstart[g], e = g_gstart[g + 1];
    float acc = 0.f;
    for (int i = s; i < e; i++)
        acc += __half2float(h[(size_t)i * CH + t]);
    const float iv = 1.0f / (float)max(e - s, 1);
    const float p = acc * iv;
    __shared__ float r0[128], r1[128];
    r0[t] = p * hW[t * 2 + 0];
    r1[t] = p * hW[t * 2 + 1];
    __syncthreads();
    #pragma unroll
    for (int o = 64; o > 0; o >>= 1) {
        if (t < o) { r0[t] += r0[t + o]; r1[t] += r1[t + o]; }
        __syncthreads();
    }
    if (t == 0) {
        out[g * 2 + 0] = r0[0] + hb[0];
        out[g * 2 + 1] = r1[0] + hb[1];
    }
}

// ---------------------------------------------------------------------------
// Host launch
// ---------------------------------------------------------------------------
static void* sym_addr(const void* sym) {
    void* p = nullptr;
    cudaGetSymbolAddress(&p, sym);
    return p;
}

extern "C" void kernel_launch(void* const* d_in, const int* in_sizes, int n_in,
                              void* d_out, int out_size) {
    const float* x    = (const float*)d_in[0];
    const int*   ei   = (const int*)d_in[1];
    const int*   srcp = ei;
    const int*   dstp = ei + EE;
    const int*   batch = (const int*)d_in[2];
    const float* Wl0 = (const float*)d_in[3];
    const float* Wr0 = (const float*)d_in[4];
    const float* b0  = (const float*)d_in[5];
    const float* Wl  = (const float*)d_in[6];
    const float* Wr  = (const float*)d_in[7];
    const float* bb  = (const float*)d_in[8];
    const float* hW  = (const float*)d_in[9];
    const float* hb  = (const float*)d_in[10];
    float* out = (float*)d_out;

    __half* h16A  = (__half*)sym_addr(g_h16A);
    __half* h16B  = (__half*)sym_addr(g_h16B);
    __half* agg16 = (__half*)sym_addr(g_agg16);
    __half* x16   = (__half*)sym_addr(g_x16);
    __half* W16   = (__half*)sym_addr(g_W16);

    static int attr_set = 0;
    if (!attr_set) {
        cudaFuncSetAttribute(k_gemm16<64, 1>,  cudaFuncAttributeMaxDynamicSharedMemorySize, SMEM_GEMM);
        cudaFuncSetAttribute(k_gemm16<128, 0>, cudaFuncAttributeMaxDynamicSharedMemorySize, SMEM_GEMM);
        cudaFuncSetAttribute(k_gemm16<128, 1>, cudaFuncAttributeMaxDynamicSharedMemorySize, SMEM_GEMM);
        cudaFuncSetAttribute(k_gemm16<128, 2>, cudaFuncAttributeMaxDynamicSharedMemorySize, SMEM_GEMM);
        attr_set = 1;
    }

    const int TPB = 256;

    // --- setup: prep (zero deg + cvt + W16 + gstart) -> count -> scan -> fill
    k_prep<<<(NN * CIN + TPB - 1) / TPB, TPB>>>(x, batch, Wl0, Wr0, Wl, Wr);
    k_count<<<(EE + TPB - 1) / TPB, TPB>>>(dstp);
    k_scan3<<<1, 1024>>>();
    k_fill<<<(EE + TPB - 1) / TPB, TPB>>>(srcp, dstp);

    const int aggBlocks = (NN * 32 + TPB - 1) / TPB;

    // --- conv 0 (C_IN=64 -> 128), ReLU ---
    k_agg16<64><<<aggBlocks, TPB>>>(x16, agg16);
    k_gemm16<64, 1><<<GEMM_BLOCKS, TPB, SMEM_GEMM>>>(agg16, x16, W16, b0, h16A);

    // --- convs 1..11 ---
    __half* hcur = h16A;
    __half* hnxt = h16B;
    for (int i = 0; i < 11; i++) {
        int ci = i + 1;
        k_agg16<128><<<aggBlocks, TPB>>>(hcur, agg16);
        const __half* wt = W16 + (size_t)(i + 1) * 128 * 256;
        const float* bi = bb + (size_t)i * CH;
        if (ci == 11) {
            k_gemm16<128, 0><<<GEMM_BLOCKS, TPB, SMEM_GEMM>>>(agg16, hcur, wt, bi, hnxt);
        } else if (ci == 3 || ci == 7) {
            k_gemm16<128, 2><<<GEMM_BLOCKS, TPB, SMEM_GEMM>>>(agg16, hcur, wt, bi, hnxt);
        } else {
            k_gemm16<128, 1><<<GEMM_BLOCKS, TPB, SMEM_GEMM>>>(agg16, hcur, wt, bi, hnxt);
        }
        __half* t = hcur; hcur = hnxt; hnxt = t;
    }

    // --- fused global mean pool + head ---
    k_poolhead<<<GG, 128>>>(hcur, hW, hb, out);
}